// round 11
// baseline (speedup 1.0000x reference)
#include <cuda_runtime.h>

// ---------------------------------------------------------------------------
// RelationOnSpatial, algebraically collapsed:
//   f = softmax(s_theta[:,None]+s_phi[None,:],axis=1) == softmax(s_phi)
//   (theta path dead, all output rows identical; constant bias cancels).
//   z[i,c] = gamma * ( g_w[c,:,:] . q / S + g_b[c] )
//   q[cy,ky,kx] = sum_{h,w} y[cy,h,w] * e[h+1-ky, w+1-kx],  e=exp(s_phi), S=sum e
// Inner loops use packed fma.rn.f32x2 (dual-FP32 path, PTX-only).
// ---------------------------------------------------------------------------

#define CY   256
#define H    128
#define WW   128
#define HW   16384
#define KEL  2304            // CY*9

__device__ float d_phi_part[32 * KEL];                // kA partials (32 chunks)
__device__ __align__(16) float d_sphi_part[32 * HW];  // conv partials per chunk
__device__ __align__(16) float d_e[HW];
__device__ float d_Spart[64];
__device__ float d_qe_w[16 * KEL];                    // per-strip q partials
__device__ __align__(16) float d_q[KEL];
__device__ __align__(16) float d_r[256];

union F2U { float2 f; unsigned long long u; };

__device__ __forceinline__ float2 ffma2(float2 a, float2 b, float2 c) {
    F2U A, B, C, D;
    A.f = a; B.f = b; C.f = c;
    asm("fma.rn.f32x2 %0, %1, %2, %3;"
        : "=l"(D.u) : "l"(A.u), "l"(B.u), "l"(C.u));
    return D.f;
}

// ---------------------------------------------------------------------------
// A: phi_eff partials over 32 chunks of 8 summed channels.  grid (9,32) x 256.
// ---------------------------------------------------------------------------
__global__ void kA(const float* __restrict__ phi_w,
                   const float* __restrict__ concat_w) {
    const int t   = threadIdx.x;
    const int out = blockIdx.x * 256 + t;
    const int p   = blockIdx.y;
    const float* wp = concat_w + 256;
    float s = 0.f;
    #pragma unroll
    for (int c = p * 8; c < p * 8 + 8; ++c)
        s += wp[c] * phi_w[c * KEL + out];
    d_phi_part[p * KEL + out] = s;
}

// ---------------------------------------------------------------------------
// B: 256ch -> 1ch 3x3 conv partials. grid (16 strips, 32 chunks of 8ch) x 256.
// Warp w owns channel chunk*8+w, sliding down the 8-row strip. Packed f32x2
// FMAs; cross-channel sum staged via disjoint smem tiles (fixed order).
// ---------------------------------------------------------------------------
__global__ void __launch_bounds__(256, 3) kB(const float* __restrict__ y) {
    __shared__ float kk[72];
    __shared__ __align__(16) float acc_sm[8][8][128];   // [warp][row][col]
    const int t = threadIdx.x;
    const int strip = blockIdx.x, chunk = blockIdx.y;

    if (t < 72) {
        float s = 0.f;
        #pragma unroll
        for (int p = 0; p < 32; ++p) s += d_phi_part[p * KEL + chunk * 72 + t];
        kk[t] = s;
    }
    __syncthreads();

    const int w = t >> 5, g = t & 31;
    const int cy = chunk * 8 + w;
    const int r0 = strip * 8;

    float2 kp[9];
    #pragma unroll
    for (int k = 0; k < 9; ++k) {
        const float kv = kk[w * 9 + k];
        kp[k] = make_float2(kv, kv);
    }

    float2 accP[8][2];
    #pragma unroll
    for (int o = 0; o < 8; ++o) {
        accP[o][0] = make_float2(0.f, 0.f);
        accP[o][1] = make_float2(0.f, 0.f);
    }

    const float* yb = y + cy * HW + 4 * g;

    // loaded row j = global row r0-1+j; contributes as tap ky to lo = j - ky.
    #pragma unroll
    for (int j = 0; j < 10; ++j) {
        const int lr = r0 - 1 + j;
        float4 V = make_float4(0.f, 0.f, 0.f, 0.f);
        if (lr >= 0 && lr < H) V = *(const float4*)(yb + lr * WW);
        float L = __shfl_up_sync(~0u, V.w, 1);   if (g == 0)  L = 0.f;
        float R = __shfl_down_sync(~0u, V.x, 1); if (g == 31) R = 0.f;
        const float2 VA = make_float2(V.x, V.y);   // aligned, free
        const float2 VB = make_float2(V.z, V.w);   // aligned, free
        const float2 P0 = make_float2(L,   V.x);
        const float2 P2 = make_float2(V.y, V.z);
        const float2 P4 = make_float2(V.w, R);
        #pragma unroll
        for (int ky = 0; ky < 3; ++ky) {
            const int lo = j - ky;
            if (lo >= 0 && lo < 8) {
                accP[lo][0] = ffma2(kp[ky*3+0], P0,
                              ffma2(kp[ky*3+1], VA,
                              ffma2(kp[ky*3+2], P2, accP[lo][0])));
                accP[lo][1] = ffma2(kp[ky*3+0], P2,
                              ffma2(kp[ky*3+1], VB,
                              ffma2(kp[ky*3+2], P4, accP[lo][1])));
            }
        }
    }

    #pragma unroll
    for (int o = 0; o < 8; ++o) {
        *(float2*)&acc_sm[w][o][4 * g]     = accP[o][0];
        *(float2*)&acc_sm[w][o][4 * g + 2] = accP[o][1];
    }
    __syncthreads();

    // warp w reduces output row w across the 8 channel buffers
    float4 s = make_float4(0.f, 0.f, 0.f, 0.f);
    #pragma unroll
    for (int b = 0; b < 8; ++b) {
        const float4 v = *(const float4*)&acc_sm[b][w][4 * g];
        s.x += v.x; s.y += v.y; s.z += v.z; s.w += v.w;
    }
    *(float4*)&d_sphi_part[chunk * HW + (r0 + w) * WW + 4 * g] = s;
}

// ---------------------------------------------------------------------------
// C: e = exp(sum of 32 chunk partials); S partials.  grid 64 x 256.
// 4 threads cooperate per float4-element (each sums 8 chunks, LDG.128).
// ---------------------------------------------------------------------------
__global__ void kC() {
    __shared__ __align__(16) float4 buf[4][64];
    __shared__ float red[2];
    const int t = threadIdx.x;
    const int lq  = t & 63;          // local quad 0..63
    const int sub = t >> 6;          // 0..3
    const int q4  = blockIdx.x * 64 + lq;

    float4 s = make_float4(0.f, 0.f, 0.f, 0.f);
    #pragma unroll
    for (int p = sub * 8; p < sub * 8 + 8; ++p) {
        const float4 v = ((const float4*)(d_sphi_part + p * HW))[q4];
        s.x += v.x; s.y += v.y; s.z += v.z; s.w += v.w;
    }
    buf[sub][lq] = s;
    __syncthreads();

    float v = 0.f;
    if (t < 64) {
        const float4 a = buf[0][t], b = buf[1][t], c = buf[2][t], d = buf[3][t];
        float4 e;
        e.x = __expf(a.x + b.x + c.x + d.x);
        e.y = __expf(a.y + b.y + c.y + d.y);
        e.z = __expf(a.z + b.z + c.z + d.z);
        e.w = __expf(a.w + b.w + c.w + d.w);
        ((float4*)d_e)[blockIdx.x * 64 + t] = e;
        v = e.x + e.y + e.z + e.w;
        #pragma unroll
        for (int o = 16; o; o >>= 1) v += __shfl_xor_sync(~0u, v, o);
        if ((t & 31) == 0) red[t >> 5] = v;
    }
    __syncthreads();
    if (t == 0) d_Spart[blockIdx.x] = red[0] + red[1];
}

// ---------------------------------------------------------------------------
// D: q partials. grid (16 strips of 8 rows, 32 channel-octets) x 256.
// Warp w owns channel oct*8+w over the 8-row strip. All 8 y rows preloaded;
// loop over tile rows (accumulators row-invariant -> no window slide);
// packed f32x2 FMAs; one 9-value butterfly per warp.
// ---------------------------------------------------------------------------
__global__ void __launch_bounds__(256, 3) kD(const float* __restrict__ y) {
    __shared__ __align__(16) float sm[10 * 132];
    __shared__ float redsm[72];
    const int t = threadIdx.x;
    const int strip = blockIdx.x;   // 0..15
    const int oct   = blockIdx.y;   // 0..31
    const int h0 = strip * 8;

    // vectorized fill: tile row rr = global e-row h0-1+rr, data at col+1
    #pragma unroll
    for (int i = t; i < 320; i += 256) {
        const int rr = i >> 5, gg = i & 31;
        const int gr = h0 - 1 + rr;
        float4 v = make_float4(0.f, 0.f, 0.f, 0.f);
        if (gr >= 0 && gr < H) v = *(const float4*)(d_e + gr * WW + 4 * gg);
        float* dst = &sm[rr * 132 + 1 + 4 * gg];
        dst[0] = v.x; dst[1] = v.y; dst[2] = v.z; dst[3] = v.w;
    }
    if (t < 20) {                     // col pads: e[-1] and e[128]
        const int rr = t >> 1;
        sm[rr * 132 + ((t & 1) ? 129 : 0)] = 0.f;
    }
    __syncthreads();

    const int w = t >> 5, g = t & 31;
    const int cy = oct * 8 + w;
    const float* yb = y + cy * HW + h0 * WW + 4 * g;

    // preload all 8 y rows (independent LDG.128)
    float4 yv[8];
    #pragma unroll
    for (int j = 0; j < 8; ++j) yv[j] = *(const float4*)(yb + j * WW);

    float2 ap[9];
    #pragma unroll
    for (int k = 0; k < 9; ++k) ap[k] = make_float2(0.f, 0.f);

    // tile row tr serves y row j = tr - ww with ky = 2 - ww
    #pragma unroll
    for (int tr = 0; tr < 10; ++tr) {
        const float* bp = &sm[tr * 132 + 4 * g];
        const float4 E0 = *(const float4*)bp;
        const float2 C  = *(const float2*)(bp + 4);
        const float2 A  = make_float2(E0.x, E0.y);   // aligned, free
        const float2 B  = make_float2(E0.z, E0.w);   // aligned, free
        const float2 O1 = make_float2(E0.y, E0.z);
        const float2 O2 = make_float2(E0.w, C.x);
        #pragma unroll
        for (int ww = 0; ww < 3; ++ww) {
            const int j = tr - ww;
            if (j >= 0 && j < 8) {
                const int ky = 2 - ww;
                const float2 yp0 = make_float2(yv[j].x, yv[j].y);
                const float2 yp1 = make_float2(yv[j].z, yv[j].w);
                ap[3*ky+2] = ffma2(yp1, B,  ffma2(yp0, A,  ap[3*ky+2]));
                ap[3*ky+1] = ffma2(yp1, O2, ffma2(yp0, O1, ap[3*ky+1]));
                ap[3*ky+0] = ffma2(yp1, C,  ffma2(yp0, B,  ap[3*ky+0]));
            }
        }
    }

    float a[9];
    #pragma unroll
    for (int k = 0; k < 9; ++k) a[k] = ap[k].x + ap[k].y;

    #pragma unroll
    for (int k = 0; k < 9; ++k)
        #pragma unroll
        for (int o = 16; o; o >>= 1)
            a[k] += __shfl_xor_sync(~0u, a[k], o);

    if (g == 0) {
        #pragma unroll
        for (int k = 0; k < 9; ++k) redsm[w * 9 + k] = a[k];
    }
    __syncthreads();
    if (t < 72) {
        const int ch = t / 9, k = t - ch * 9;
        d_qe_w[strip * KEL + (oct * 8 + ch) * 9 + k] = redsm[t];
    }
}

// ---------------------------------------------------------------------------
// E0: q[j] = sum over 16 strips.  grid 9 x 256.
// ---------------------------------------------------------------------------
__global__ void kE0() {
    const int j = blockIdx.x * 256 + threadIdx.x;
    float s = 0.f;
    #pragma unroll
    for (int sb = 0; sb < 16; ++sb) s += d_qe_w[sb * KEL + j];
    d_q[j] = s;
}

// ---------------------------------------------------------------------------
// E: r[c] = gamma*(g_w[c,:].q / S + g_b[c]).  256 blocks x 256.
// ---------------------------------------------------------------------------
__global__ void kE(const float* __restrict__ g_w,
                   const float* __restrict__ g_b,
                   const float* __restrict__ gamma) {
    __shared__ float red[256];
    const int c = blockIdx.x, t = threadIdx.x;
    const float4* gw4 = (const float4*)(g_w + c * KEL);
    const float4* q4  = (const float4*)d_q;
    float s = 0.f;
    for (int j = t; j < 576; j += 256) {
        const float4 gv = gw4[j];
        const float4 qv = q4[j];
        s += gv.x * qv.x + gv.y * qv.y + gv.z * qv.z + gv.w * qv.w;
    }
    red[t] = s;
    __syncthreads();
    for (int o = 128; o > 0; o >>= 1) {
        if (t < o) red[t] += red[t + o];
        __syncthreads();
    }
    if (t == 0) {
        float S = 0.f;
        #pragma unroll
        for (int i = 0; i < 64; ++i) S += d_Spart[i];
        d_r[c] = gamma[0] * (red[0] / S + g_b[c]);
    }
}

// ---------------------------------------------------------------------------
// F: broadcast r to 1024 rows, float4.  256 x 256.
// ---------------------------------------------------------------------------
__global__ void kF(float* __restrict__ out) {
    const int i = blockIdx.x * 256 + threadIdx.x;
    ((float4*)out)[i] = ((const float4*)d_r)[i & 63];
}

extern "C" void kernel_launch(void* const* d_in, const int* in_sizes, int n_in,
                              void* d_out, int out_size) {
    // order: x, y, g_w, g_b, phi_w, phi_b, theta_w, theta_b, concat_w, gamma
    const float* y        = (const float*)d_in[1];
    const float* g_w      = (const float*)d_in[2];
    const float* g_b      = (const float*)d_in[3];
    const float* phi_w    = (const float*)d_in[4];
    const float* concat_w = (const float*)d_in[8];
    const float* gamma    = (const float*)d_in[9];

    kA<<<dim3(9, 32), 256>>>(phi_w, concat_w);
    kB<<<dim3(16, 32), 256>>>(y);
    kC<<<64, 256>>>();
    kD<<<dim3(16, 32), 256>>>(y);
    kE0<<<9, 256>>>();
    kE<<<256, 256>>>(g_w, g_b, gamma);
    kF<<<256, 256>>>((float*)d_out);
}

// round 12
// speedup vs baseline: 1.0089x; 1.0089x over previous
#include <cuda_runtime.h>

// ---------------------------------------------------------------------------
// RelationOnSpatial, algebraically collapsed:
//   f = softmax(s_theta[:,None]+s_phi[None,:],axis=1) == softmax(s_phi)
//   (theta path dead, all output rows identical; constant bias cancels).
//   z[i,c] = gamma * ( g_w[c,:,:] . q / S + g_b[c] )
//   q[cy,ky,kx] = sum_{h,w} y[cy,h,w] * e[h+1-ky, w+1-kx],  e=exp(s_phi), S=sum e
// ---------------------------------------------------------------------------

#define CY   256
#define H    128
#define WW   128
#define HW   16384
#define KEL  2304            // CY*9

__device__ float d_phi_part[32 * KEL];                // kA partials (32 chunks)
__device__ __align__(16) float d_sphi_part[32 * HW];  // conv partials per chunk
__device__ __align__(16) float d_e[HW];
__device__ float d_Spart[64];
__device__ float d_qe_w[16 * KEL];                    // per-strip q partials
__device__ __align__(16) float d_q[KEL];
__device__ __align__(16) float d_r[256];

// ---------------------------------------------------------------------------
// A: phi_eff partials over 32 chunks of 8 summed channels.  grid (9,32) x 256.
// ---------------------------------------------------------------------------
__global__ void kA(const float* __restrict__ phi_w,
                   const float* __restrict__ concat_w) {
    const int t   = threadIdx.x;
    const int out = blockIdx.x * 256 + t;
    const int p   = blockIdx.y;
    const float* wp = concat_w + 256;
    float s = 0.f;
    #pragma unroll
    for (int c = p * 8; c < p * 8 + 8; ++c)
        s += wp[c] * phi_w[c * KEL + out];
    d_phi_part[p * KEL + out] = s;
}

// ---------------------------------------------------------------------------
// B: 256ch -> 1ch 3x3 conv partials. grid (16 strips, 32 chunks of 8ch) x 256.
// Warp w owns channel chunk*8+w, sliding down the 8-row strip. y rows loaded
// in two batches of 5 (MLP=5), then shuffles, then FMAs. Cross-channel sum
// staged via disjoint smem tiles (fixed order).
// ---------------------------------------------------------------------------
__global__ void __launch_bounds__(256, 3) kB(const float* __restrict__ y) {
    __shared__ float kk[72];
    __shared__ __align__(16) float acc_sm[8][8][128];   // [warp][row][col]
    const int t = threadIdx.x;
    const int strip = blockIdx.x, chunk = blockIdx.y;

    if (t < 72) {
        float s = 0.f;
        #pragma unroll
        for (int p = 0; p < 32; ++p) s += d_phi_part[p * KEL + chunk * 72 + t];
        kk[t] = s;
    }
    __syncthreads();

    const int w = t >> 5, g = t & 31;
    const int cy = chunk * 8 + w;
    const int r0 = strip * 8;

    float k9[9];
    #pragma unroll
    for (int k = 0; k < 9; ++k) k9[k] = kk[w * 9 + k];

    float4 acc[8];
    #pragma unroll
    for (int o = 0; o < 8; ++o) acc[o] = make_float4(0.f, 0.f, 0.f, 0.f);

    const float* yb = y + cy * HW + 4 * g;
    const float4 Z = make_float4(0.f, 0.f, 0.f, 0.f);

    // rows processed in two batches of 5: loads first (MLP=5), then shfl+FMA.
    // loaded row j covers global row r0-1+j; tap ky -> local out lo = j - ky.
    #pragma unroll
    for (int jb = 0; jb < 2; ++jb) {
        float4 V[5]; float L[5], R[5];
        #pragma unroll
        for (int i = 0; i < 5; ++i) {
            const int lr = r0 - 1 + jb * 5 + i;
            V[i] = (lr >= 0 && lr < H) ? *(const float4*)(yb + lr * WW) : Z;
        }
        #pragma unroll
        for (int i = 0; i < 5; ++i) {
            L[i] = __shfl_up_sync(~0u, V[i].w, 1);   if (g == 0)  L[i] = 0.f;
            R[i] = __shfl_down_sync(~0u, V[i].x, 1); if (g == 31) R[i] = 0.f;
        }
        #pragma unroll
        for (int i = 0; i < 5; ++i) {
            const int j = jb * 5 + i;
            #pragma unroll
            for (int ky = 0; ky < 3; ++ky) {
                const int lo = j - ky;
                if (lo >= 0 && lo < 8) {
                    const float k0 = k9[ky * 3 + 0];
                    const float k1 = k9[ky * 3 + 1];
                    const float k2 = k9[ky * 3 + 2];
                    acc[lo].x += k0 * L[i]   + k1 * V[i].x + k2 * V[i].y;
                    acc[lo].y += k0 * V[i].x + k1 * V[i].y + k2 * V[i].z;
                    acc[lo].z += k0 * V[i].y + k1 * V[i].z + k2 * V[i].w;
                    acc[lo].w += k0 * V[i].z + k1 * V[i].w + k2 * R[i];
                }
            }
        }
    }

    #pragma unroll
    for (int o = 0; o < 8; ++o)
        *(float4*)&acc_sm[w][o][4 * g] = acc[o];
    __syncthreads();

    // warp w reduces output row w across the 8 channel buffers
    float4 s = make_float4(0.f, 0.f, 0.f, 0.f);
    #pragma unroll
    for (int b = 0; b < 8; ++b) {
        const float4 v = *(const float4*)&acc_sm[b][w][4 * g];
        s.x += v.x; s.y += v.y; s.z += v.z; s.w += v.w;
    }
    *(float4*)&d_sphi_part[chunk * HW + (r0 + w) * WW + 4 * g] = s;
}

// ---------------------------------------------------------------------------
// C: e = exp(sum of 32 chunk partials); S partials.  grid 64 x 256.
// 4 threads cooperate per float4-element (each sums 8 chunks, LDG.128).
// ---------------------------------------------------------------------------
__global__ void kC() {
    __shared__ __align__(16) float4 buf[4][64];
    __shared__ float red[2];
    const int t = threadIdx.x;
    const int lq  = t & 63;          // local quad 0..63
    const int sub = t >> 6;          // 0..3
    const int q4  = blockIdx.x * 64 + lq;

    float4 s = make_float4(0.f, 0.f, 0.f, 0.f);
    #pragma unroll
    for (int p = sub * 8; p < sub * 8 + 8; ++p) {
        const float4 v = ((const float4*)(d_sphi_part + p * HW))[q4];
        s.x += v.x; s.y += v.y; s.z += v.z; s.w += v.w;
    }
    buf[sub][lq] = s;
    __syncthreads();

    float v = 0.f;
    if (t < 64) {
        const float4 a = buf[0][t], b = buf[1][t], c = buf[2][t], d = buf[3][t];
        float4 e;
        e.x = __expf(a.x + b.x + c.x + d.x);
        e.y = __expf(a.y + b.y + c.y + d.y);
        e.z = __expf(a.z + b.z + c.z + d.z);
        e.w = __expf(a.w + b.w + c.w + d.w);
        ((float4*)d_e)[blockIdx.x * 64 + t] = e;
        v = e.x + e.y + e.z + e.w;
        #pragma unroll
        for (int o = 16; o; o >>= 1) v += __shfl_xor_sync(~0u, v, o);
        if ((t & 31) == 0) red[t >> 5] = v;
    }
    __syncthreads();
    if (t == 0) d_Spart[blockIdx.x] = red[0] + red[1];
}

// ---------------------------------------------------------------------------
// D: q partials. grid (16 strips of 8 rows, 32 channel-octets) x 256.
// Warp w owns channel oct*8+w over the 8-row strip. y rows preloaded BEFORE
// the e-tile fill so their latency hides behind fill+barrier; e-window
// slides in registers; one 9-value butterfly per warp.
// ---------------------------------------------------------------------------
__global__ void __launch_bounds__(256, 4) kD(const float* __restrict__ y) {
    __shared__ __align__(16) float sm[10 * 132];
    __shared__ float redsm[72];
    const int t = threadIdx.x;
    const int strip = blockIdx.x;   // 0..15
    const int oct   = blockIdx.y;   // 0..31
    const int h0 = strip * 8;

    const int w = t >> 5, g = t & 31;
    const int cy = oct * 8 + w;
    const float* yb = y + cy * HW + h0 * WW + 4 * g;

    // preload all 8 y rows FIRST (independent of smem; overlaps fill+sync)
    float4 yv[8];
    #pragma unroll
    for (int j = 0; j < 8; ++j) yv[j] = *(const float4*)(yb + j * WW);

    // vectorized fill: tile row rr = global e-row h0-1+rr, data at col+1
    #pragma unroll
    for (int i = t; i < 320; i += 256) {
        const int rr = i >> 5, gg = i & 31;
        const int gr = h0 - 1 + rr;
        float4 v = make_float4(0.f, 0.f, 0.f, 0.f);
        if (gr >= 0 && gr < H) v = *(const float4*)(d_e + gr * WW + 4 * gg);
        float* dst = &sm[rr * 132 + 1 + 4 * gg];
        dst[0] = v.x; dst[1] = v.y; dst[2] = v.z; dst[3] = v.w;
    }
    if (t < 20) {                     // col pads: e[-1] and e[128]
        const int rr = t >> 1;
        sm[rr * 132 + ((t & 1) ? 129 : 0)] = 0.f;
    }
    __syncthreads();

    float a[9];
    #pragma unroll
    for (int k = 0; k < 9; ++k) a[k] = 0.f;

    // sliding e-window: W[ww] = tile row (j + ww); ky = 2 - ww
    float4 E0[3]; float2 E1[3];
    #pragma unroll
    for (int j = 0; j < 3; ++j) {
        const float* bp = &sm[j * 132 + 4 * g];
        E0[j] = *(const float4*)bp;
        E1[j] = *(const float2*)(bp + 4);
    }

    #pragma unroll
    for (int j = 0; j < 8; ++j) {
        #pragma unroll
        for (int ww = 0; ww < 3; ++ww) {
            const int ky = 2 - ww;
            a[3*ky+2] += yv[j].x*E0[ww].x + yv[j].y*E0[ww].y + yv[j].z*E0[ww].z + yv[j].w*E0[ww].w;
            a[3*ky+1] += yv[j].x*E0[ww].y + yv[j].y*E0[ww].z + yv[j].z*E0[ww].w + yv[j].w*E1[ww].x;
            a[3*ky+0] += yv[j].x*E0[ww].z + yv[j].y*E0[ww].w + yv[j].z*E1[ww].x + yv[j].w*E1[ww].y;
        }
        if (j < 7) {
            E0[0] = E0[1]; E1[0] = E1[1];
            E0[1] = E0[2]; E1[1] = E1[2];
            const float* bp = &sm[(j + 3) * 132 + 4 * g];
            E0[2] = *(const float4*)bp;
            E1[2] = *(const float2*)(bp + 4);
        }
    }

    #pragma unroll
    for (int k = 0; k < 9; ++k)
        #pragma unroll
        for (int o = 16; o; o >>= 1)
            a[k] += __shfl_xor_sync(~0u, a[k], o);

    if (g == 0) {
        #pragma unroll
        for (int k = 0; k < 9; ++k) redsm[w * 9 + k] = a[k];
    }
    __syncthreads();
    if (t < 72) {
        const int ch = t / 9, k = t - ch * 9;
        d_qe_w[strip * KEL + (oct * 8 + ch) * 9 + k] = redsm[t];
    }
}

// ---------------------------------------------------------------------------
// E0: q[j] = sum over 16 strips.  grid 9 x 256.
// ---------------------------------------------------------------------------
__global__ void kE0() {
    const int j = blockIdx.x * 256 + threadIdx.x;
    float s = 0.f;
    #pragma unroll
    for (int sb = 0; sb < 16; ++sb) s += d_qe_w[sb * KEL + j];
    d_q[j] = s;
}

// ---------------------------------------------------------------------------
// E: r[c] = gamma*(g_w[c,:].q / S + g_b[c]).  256 blocks x 256.
// ---------------------------------------------------------------------------
__global__ void kE(const float* __restrict__ g_w,
                   const float* __restrict__ g_b,
                   const float* __restrict__ gamma) {
    __shared__ float red[256];
    const int c = blockIdx.x, t = threadIdx.x;
    const float4* gw4 = (const float4*)(g_w + c * KEL);
    const float4* q4  = (const float4*)d_q;
    float s = 0.f;
    for (int j = t; j < 576; j += 256) {
        const float4 gv = gw4[j];
        const float4 qv = q4[j];
        s += gv.x * qv.x + gv.y * qv.y + gv.z * qv.z + gv.w * qv.w;
    }
    red[t] = s;
    __syncthreads();
    for (int o = 128; o > 0; o >>= 1) {
        if (t < o) red[t] += red[t + o];
        __syncthreads();
    }
    if (t == 0) {
        float S = 0.f;
        #pragma unroll
        for (int i = 0; i < 64; ++i) S += d_Spart[i];
        d_r[c] = gamma[0] * (red[0] / S + g_b[c]);
    }
}

// ---------------------------------------------------------------------------
// F: broadcast r to 1024 rows, float4.  256 x 256.
// ---------------------------------------------------------------------------
__global__ void kF(float* __restrict__ out) {
    const int i = blockIdx.x * 256 + threadIdx.x;
    ((float4*)out)[i] = ((const float4*)d_r)[i & 63];
}

extern "C" void kernel_launch(void* const* d_in, const int* in_sizes, int n_in,
                              void* d_out, int out_size) {
    // order: x, y, g_w, g_b, phi_w, phi_b, theta_w, theta_b, concat_w, gamma
    const float* y        = (const float*)d_in[1];
    const float* g_w      = (const float*)d_in[2];
    const float* g_b      = (const float*)d_in[3];
    const float* phi_w    = (const float*)d_in[4];
    const float* concat_w = (const float*)d_in[8];
    const float* gamma    = (const float*)d_in[9];

    kA<<<dim3(9, 32), 256>>>(phi_w, concat_w);
    kB<<<dim3(16, 32), 256>>>(y);
    kC<<<64, 256>>>();
    kD<<<dim3(16, 32), 256>>>(y);
    kE0<<<9, 256>>>();
    kE<<<256, 256>>>(g_w, g_b, gamma);
    kF<<<256, 256>>>((float*)d_out);
}